// round 12
// baseline (speedup 1.0000x reference)
#include <cuda_runtime.h>
#include <cuda_fp16.h>
#include <cstdint>

#define FDIM 128
#define MAX_NODES 100000
#define MAX_EDGES 1600000
#define SCAN_B 1024
#define MAX_SCAN_BLOCKS ((MAX_NODES + SCAN_B - 1) / SCAN_B)

// ---------------- scratch (device globals: allocation-free rule) ----------------
__device__ __align__(16) __half g_hA[(size_t)MAX_NODES * FDIM];
__device__ __align__(16) __half g_hB[(size_t)MAX_NODES * FDIM];
__device__ float g_isq[MAX_NODES];
__device__ int   g_cnt[MAX_NODES];
__device__ int   g_lpos[MAX_EDGES];
__device__ int   g_rowptr[MAX_NODES + 1];
__device__ int   g_partial[MAX_SCAN_BLOCKS + 1];
__device__ int2  g_epack[MAX_EDGES];
__device__ __align__(16) __half g_wt1[128 * 136];
__device__ __align__(16) __half g_wt2[128 * 136];
__device__ __align__(16) __half g_wtf[64 * 136];   // fused W3@Wout, transposed
__device__ float g_bf[64];                          // fused b3@Wout + bout

// ---------------- CSR build ----------------
__global__ void zero_kernel(int* __restrict__ cnt, int n) {
    int i = blockIdx.x * blockDim.x + threadIdx.x;
    if (i < n) cnt[i] = 0;
}
__global__ void count_kernel(const int* __restrict__ dst, int* __restrict__ cnt,
                             int* __restrict__ lpos, int E) {
    int e = blockIdx.x * blockDim.x + threadIdx.x;
    if (e < E) lpos[e] = atomicAdd(&cnt[dst[e]], 1);
}
// block scan + isq fused (both read cnt)
__global__ void block_scan_kernel(const int* __restrict__ cnt, int* __restrict__ rowptr,
                                  int* __restrict__ partial, float* __restrict__ isq, int n) {
    __shared__ int sh[SCAN_B];
    int i = blockIdx.x * SCAN_B + threadIdx.x;
    int v = (i < n) ? cnt[i] : 0;
    if (i < n) isq[i] = rsqrtf((float)(v + 1));
    sh[threadIdx.x] = v;
    __syncthreads();
#pragma unroll
    for (int off = 1; off < SCAN_B; off <<= 1) {
        int t = (threadIdx.x >= off) ? sh[threadIdx.x - off] : 0;
        __syncthreads();
        sh[threadIdx.x] += t;
        __syncthreads();
    }
    if (i < n) rowptr[i] = sh[threadIdx.x] - v;
    if (threadIdx.x == SCAN_B - 1) partial[blockIdx.x] = sh[SCAN_B - 1];
}
__global__ void partial_scan_kernel(int* __restrict__ partial, int nb) {
    int lane = threadIdx.x;   // 32 threads
    int base = lane * 4;
    int v0 = (base + 0 < nb) ? partial[base + 0] : 0;
    int v1 = (base + 1 < nb) ? partial[base + 1] : 0;
    int v2 = (base + 2 < nb) ? partial[base + 2] : 0;
    int v3 = (base + 3 < nb) ? partial[base + 3] : 0;
    int tot = v0 + v1 + v2 + v3;
    int x = tot;
#pragma unroll
    for (int off = 1; off < 32; off <<= 1) {
        int y = __shfl_up_sync(0xFFFFFFFF, x, off);
        if (lane >= off) x += y;
    }
    int run = x - tot;
    if (base + 0 < nb) partial[base + 0] = run;            run += v0;
    if (base + 1 < nb) partial[base + 1] = run;            run += v1;
    if (base + 2 < nb) partial[base + 2] = run;            run += v2;
    if (base + 3 < nb) partial[base + 3] = run;
    if (lane == 31) partial[nb] = x;
}
__global__ void add_offsets_kernel(int* __restrict__ rowptr, const int* __restrict__ partial,
                                   int n, int nb) {
    int i = blockIdx.x * blockDim.x + threadIdx.x;
    if (i < n) rowptr[i] += partial[i / SCAN_B];
    if (i == 0) rowptr[n] = partial[nb];
}
__global__ void fill_kernel(const int* __restrict__ src, const int* __restrict__ dst,
                            const float* __restrict__ isq, const int* __restrict__ rowptr,
                            const int* __restrict__ lpos, int2* __restrict__ epack, int E) {
    int e = blockIdx.x * blockDim.x + threadIdx.x;
    if (e >= E) return;
    int s = src[e], d = dst[e];
    epack[rowptr[d] + lpos[e]] = make_int2(s, __float_as_int(isq[s] * isq[d]));
}

// ---------------- merged W prep: wt1, wt2, wtf=W3@Wout, bf=b3@Wout+bout ----------
__global__ void prep_all_kernel(const float* __restrict__ W1, const float* __restrict__ W2,
                                const float* __restrict__ W3, const float* __restrict__ Wo,
                                const float* __restrict__ b3, const float* __restrict__ bo,
                                __half* __restrict__ wt1, __half* __restrict__ wt2,
                                __half* __restrict__ wtf, float* __restrict__ bf) {
    int i = blockIdx.x * blockDim.x + threadIdx.x;
    if (i < 16384) {                         // wt1
        int k = i >> 7, nr = i & 127;
        wt1[nr * 136 + k] = __float2half_rn(W1[i]);
    } else if (i < 32768) {                  // wt2
        int j = i - 16384;
        int k = j >> 7, nr = j & 127;
        wt2[nr * 136 + k] = __float2half_rn(W2[j]);
    } else if (i < 32768 + 8192) {           // wtf = W3 @ Wout
        int j = i - 32768;
        int r = j >> 6, c = j & 63;
        float s = 0.f;
#pragma unroll 8
        for (int q = 0; q < 128; ++q) s += W3[r * 128 + q] * Wo[q * 64 + c];
        wtf[c * 136 + r] = __float2half_rn(s);
    } else if (i < 32768 + 8192 + 64) {      // bf
        int c = i - 32768 - 8192;
        float s = bo[c];
#pragma unroll 8
        for (int q = 0; q < 128; ++q) s += b3[q] * Wo[q * 64 + c];
        bf[c] = s;
    }
}

// ---------------- aggregation: warp per node, 2x-unrolled gather ----------------
template <bool RELU>
__global__ void agg_kernel(const __half* __restrict__ t, const int* __restrict__ rowptr,
                           const int2* __restrict__ epack, const float* __restrict__ isq,
                           const float* __restrict__ bias, __half* __restrict__ out, int n) {
    int node = (blockIdx.x * blockDim.x + threadIdx.x) >> 5;
    if (node >= n) return;
    int lane = threadIdx.x & 31;
    int beg = rowptr[node], end = rowptr[node + 1];
    float s = isq[node], c = s * s;

    uint2 raw = __ldg((const uint2*)(t + (size_t)node * FDIM) + lane);
    float2 f0 = __half22float2(*(half2*)&raw.x);
    float2 f1 = __half22float2(*(half2*)&raw.y);
    float4 acc = make_float4(c * f0.x, c * f0.y, c * f1.x, c * f1.y);

    int j = beg;
    for (; j + 2 <= end; j += 2) {
        int2 pa = __ldg(&epack[j]);
        int2 pb = __ldg(&epack[j + 1]);
        uint2 ra = __ldg((const uint2*)(t + (size_t)pa.x * FDIM) + lane);
        uint2 rb = __ldg((const uint2*)(t + (size_t)pb.x * FDIM) + lane);
        float wa = __int_as_float(pa.y);
        float wb = __int_as_float(pb.y);
        float2 a0 = __half22float2(*(half2*)&ra.x);
        float2 a1 = __half22float2(*(half2*)&ra.y);
        float2 b0 = __half22float2(*(half2*)&rb.x);
        float2 b1 = __half22float2(*(half2*)&rb.y);
        acc.x += wa * a0.x + wb * b0.x;
        acc.y += wa * a0.y + wb * b0.y;
        acc.z += wa * a1.x + wb * b1.x;
        acc.w += wa * a1.y + wb * b1.y;
    }
    if (j < end) {
        int2 p = __ldg(&epack[j]);
        float w = __int_as_float(p.y);
        uint2 r2 = __ldg((const uint2*)(t + (size_t)p.x * FDIM) + lane);
        float2 g0 = __half22float2(*(half2*)&r2.x);
        float2 g1 = __half22float2(*(half2*)&r2.y);
        acc.x += w * g0.x; acc.y += w * g0.y; acc.z += w * g1.x; acc.w += w * g1.y;
    }
    float4 b = __ldg((const float4*)bias + lane);
    acc.x += b.x; acc.y += b.y; acc.z += b.z; acc.w += b.w;
    if (RELU) {
        acc.x = fmaxf(acc.x, 0.f); acc.y = fmaxf(acc.y, 0.f);
        acc.z = fmaxf(acc.z, 0.f); acc.w = fmaxf(acc.w, 0.f);
    }
    uint2 o;
    *(half2*)&o.x = __floats2half2_rn(acc.x, acc.y);
    *(half2*)&o.y = __floats2half2_rn(acc.z, acc.w);
    ((uint2*)(out + (size_t)node * FDIM))[lane] = o;
}

// final agg: 64 features, fp32 output with fused bias (writes d_out directly)
__global__ void agg64_kernel(const __half* __restrict__ t, const int* __restrict__ rowptr,
                             const int2* __restrict__ epack, const float* __restrict__ isq,
                             const float* __restrict__ bias, float* __restrict__ out, int n) {
    int node = (blockIdx.x * blockDim.x + threadIdx.x) >> 5;
    if (node >= n) return;
    int lane = threadIdx.x & 31;
    int beg = rowptr[node], end = rowptr[node + 1];
    float s = isq[node], c = s * s;

    uint32_t raw = __ldg((const uint32_t*)(t + (size_t)node * 64) + lane);
    float2 f = __half22float2(*(half2*)&raw);
    float2 acc = make_float2(c * f.x, c * f.y);

    int j = beg;
    for (; j + 2 <= end; j += 2) {
        int2 pa = __ldg(&epack[j]);
        int2 pb = __ldg(&epack[j + 1]);
        uint32_t ra = __ldg((const uint32_t*)(t + (size_t)pa.x * 64) + lane);
        uint32_t rb = __ldg((const uint32_t*)(t + (size_t)pb.x * 64) + lane);
        float wa = __int_as_float(pa.y);
        float wb = __int_as_float(pb.y);
        float2 ga = __half22float2(*(half2*)&ra);
        float2 gb = __half22float2(*(half2*)&rb);
        acc.x += wa * ga.x + wb * gb.x;
        acc.y += wa * ga.y + wb * gb.y;
    }
    if (j < end) {
        int2 p = __ldg(&epack[j]);
        float w = __int_as_float(p.y);
        uint32_t r2 = __ldg((const uint32_t*)(t + (size_t)p.x * 64) + lane);
        float2 g = __half22float2(*(half2*)&r2);
        acc.x += w * g.x; acc.y += w * g.y;
    }
    float2 b = __ldg((const float2*)bias + lane);
    acc.x += b.x; acc.y += b.y;
    ((float2*)(out + (size_t)node * 64))[lane] = acc;
}

// ---------------- fp16 mma helper ----------------
__device__ __forceinline__ void mma_16n8k16(float& c0, float& c1, float& c2, float& c3,
                                            uint32_t a0, uint32_t a1, uint32_t a2, uint32_t a3,
                                            uint32_t b0, uint32_t b1) {
    asm volatile(
        "mma.sync.aligned.m16n8k16.row.col.f32.f16.f16.f32 "
        "{%0,%1,%2,%3}, {%4,%5,%6,%7}, {%8,%9}, {%0,%1,%2,%3};"
        : "+f"(c0), "+f"(c1), "+f"(c2), "+f"(c3)
        : "r"(a0), "r"(a1), "r"(a2), "r"(a3), "r"(b0), "r"(b1));
}

// ---------------- GEMM: C(half) = A[M,128] @ W ; A fp32 or fp16 ------------------
template <int N_OUT, bool A_FP32>
__global__ __launch_bounds__(256, 4)
void gemm_mma_kernel(const void* __restrict__ Ain, const __half* __restrict__ Wimg,
                     __half* __restrict__ C, int M) {
    constexpr int COLG = N_OUT / 64;
    constexpr int ROWG = 8 / COLG;
    constexpr int BM   = ROWG * 16;
    constexpr int AST  = 136;
    constexpr int KS   = 136;
    constexpr int NT   = 8;

    extern __shared__ __half smem_h[];
    __half* As = smem_h;                    // [BM][AST]
    __half* Wt = smem_h + BM * AST;         // [N_OUT][KS]

    int tid  = threadIdx.x;
    int wid  = tid >> 5;
    int lane = tid & 31;
    int g    = lane >> 2;
    int t4   = lane & 3;
    int wid_r = wid / COLG;
    int wid_c = wid % COLG;
    int row0 = blockIdx.x * BM;

    for (int i = tid; i < N_OUT * 17; i += 256)
        ((uint4*)Wt)[i] = ((const uint4*)Wimg)[i];
    for (int i = tid; i < BM * 32; i += 256) {
        int r  = i >> 5;
        int c4 = i & 31;
        int gr = row0 + r;
        uint2 v = make_uint2(0u, 0u);
        if (gr < M) {
            if (A_FP32) {
                float4 f = ((const float4*)((const float*)Ain + (size_t)gr * FDIM))[c4];
                *(half2*)&v.x = __floats2half2_rn(f.x, f.y);
                *(half2*)&v.y = __floats2half2_rn(f.z, f.w);
            } else {
                v = ((const uint2*)((const __half*)Ain + (size_t)gr * FDIM))[c4];
            }
        }
        *(uint2*)(As + r * AST + c4 * 4) = v;
    }
    __syncthreads();

    float acc[NT][4];
#pragma unroll
    for (int nt = 0; nt < NT; ++nt) {
        acc[nt][0] = 0.f; acc[nt][1] = 0.f; acc[nt][2] = 0.f; acc[nt][3] = 0.f;
    }

    const __half* arow_lo = As + (wid_r * 16 + g) * AST;
    const __half* arow_hi = arow_lo + 8 * AST;
    const int ncol0 = wid_c * 64;

#pragma unroll
    for (int ks = 0; ks < 8; ++ks) {
        int k0 = ks * 16 + 2 * t4;
        uint32_t a0 = *(const uint32_t*)(arow_lo + k0);
        uint32_t a1 = *(const uint32_t*)(arow_hi + k0);
        uint32_t a2 = *(const uint32_t*)(arow_lo + k0 + 8);
        uint32_t a3 = *(const uint32_t*)(arow_hi + k0 + 8);
        const __half* wb = Wt + (ncol0 + g) * KS + k0;
#pragma unroll
        for (int nt = 0; nt < NT; ++nt) {
            uint32_t b0 = *(const uint32_t*)(wb + nt * 8 * KS);
            uint32_t b1 = *(const uint32_t*)(wb + nt * 8 * KS + 8);
            mma_16n8k16(acc[nt][0], acc[nt][1], acc[nt][2], acc[nt][3],
                        a0, a1, a2, a3, b0, b1);
        }
    }

    int r_lo = row0 + wid_r * 16 + g;
    int r_hi = r_lo + 8;
#pragma unroll
    for (int nt = 0; nt < NT; ++nt) {
        int col = ncol0 + nt * 8 + 2 * t4;
        if (r_lo < M)
            *(half2*)(C + (size_t)r_lo * N_OUT + col) = __floats2half2_rn(acc[nt][0], acc[nt][1]);
        if (r_hi < M)
            *(half2*)(C + (size_t)r_hi * N_OUT + col) = __floats2half2_rn(acc[nt][2], acc[nt][3]);
    }
}

// ---------------- launch ----------------
extern "C" void kernel_launch(void* const* d_in, const int* in_sizes, int n_in,
                              void* d_out, int out_size) {
    const float* x   = (const float*)d_in[0];
    const int*   ei  = (const int*)d_in[1];     // int32 (JAX x64 disabled)
    const float* W1  = (const float*)d_in[2];
    const float* b1  = (const float*)d_in[3];
    const float* W2  = (const float*)d_in[4];
    const float* b2  = (const float*)d_in[5];
    const float* W3  = (const float*)d_in[6];
    const float* b3  = (const float*)d_in[7];
    const float* Wo  = (const float*)d_in[8];
    const float* bo  = (const float*)d_in[9];

    int n = in_sizes[0] / FDIM;
    int E = in_sizes[1] / 2;
    const int* src = ei;
    const int* dst = ei + E;

    __half *hA, *hB, *wt1, *wt2, *wtf;
    float *isq, *bf;
    int *cnt, *lpos, *rowptr, *partial;
    int2* epack;
    cudaGetSymbolAddress((void**)&hA,      g_hA);
    cudaGetSymbolAddress((void**)&hB,      g_hB);
    cudaGetSymbolAddress((void**)&isq,     g_isq);
    cudaGetSymbolAddress((void**)&cnt,     g_cnt);
    cudaGetSymbolAddress((void**)&lpos,    g_lpos);
    cudaGetSymbolAddress((void**)&rowptr,  g_rowptr);
    cudaGetSymbolAddress((void**)&partial, g_partial);
    cudaGetSymbolAddress((void**)&epack,   g_epack);
    cudaGetSymbolAddress((void**)&wt1,     g_wt1);
    cudaGetSymbolAddress((void**)&wt2,     g_wt2);
    cudaGetSymbolAddress((void**)&wtf,     g_wtf);
    cudaGetSymbolAddress((void**)&bf,      g_bf);

    const int SMEM = (64 * 136 + 128 * 136) * 2;   // 52,224 B
    cudaFuncSetAttribute(gemm_mma_kernel<128, true>,  cudaFuncAttributeMaxDynamicSharedMemorySize, SMEM);
    cudaFuncSetAttribute(gemm_mma_kernel<128, false>, cudaFuncAttributeMaxDynamicSharedMemorySize, SMEM);
    cudaFuncSetAttribute(gemm_mma_kernel<64, false>,  cudaFuncAttributeMaxDynamicSharedMemorySize, SMEM);

    const int T = 256;
    int nb_nodes   = (n + T - 1) / T;
    int nb_edges   = (E + T - 1) / T;
    int nb_agg     = (int)(((long long)n * 32 + T - 1) / T);
    int nb_gemm128 = (n + 63) / 64;
    int nb_gemm64  = (n + 127) / 128;
    int nb_scan    = (n + SCAN_B - 1) / SCAN_B;

    // Launch order places gemm1 in the profiler capture window (slot ~4-6)
    // while preserving dependencies (gemm1 needs only prep_all + x).
    prep_all_kernel<<<(41024 + T - 1) / T, T>>>(W1, W2, W3, Wo, b3, bo, wt1, wt2, wtf, bf); // 1
    zero_kernel<<<nb_nodes, T>>>(cnt, n);                                                   // 2
    count_kernel<<<nb_edges, T>>>(dst, cnt, lpos, E);                                       // 3
    gemm_mma_kernel<128, true><<<nb_gemm128, 256, SMEM>>>(x, wt1, hA, n);                   // 4
    block_scan_kernel<<<nb_scan, SCAN_B>>>(cnt, rowptr, partial, isq, n);                   // 5
    partial_scan_kernel<<<1, 32>>>(partial, nb_scan);                                       // 6
    add_offsets_kernel<<<nb_nodes, T>>>(rowptr, partial, n, nb_scan);                       // 7
    fill_kernel<<<nb_edges, T>>>(src, dst, isq, rowptr, lpos, epack, E);                    // 8

    // ---- layer 1 agg: h1 = relu(agg(x@W1) + b1) ----
    agg_kernel<true><<<nb_agg, T>>>(hA, rowptr, epack, isq, b1, hB, n);                     // 9
    // ---- layer 2 ----
    gemm_mma_kernel<128, false><<<nb_gemm128, 256, SMEM>>>(hB, wt2, hA, n);                 // 10
    agg_kernel<true><<<nb_agg, T>>>(hA, rowptr, epack, isq, b2, hB, n);                     // 11
    // ---- layer 3 + output fused ----
    gemm_mma_kernel<64, false><<<nb_gemm64, 256, SMEM>>>(hB, wtf, hA, n);                   // 12
    agg64_kernel<<<nb_agg, T>>>(hA, rowptr, epack, isq, bf, (float*)d_out, n);              // 13
}

// round 13
// speedup vs baseline: 1.0594x; 1.0594x over previous
#include <cuda_runtime.h>
#include <cuda_fp16.h>
#include <cstdint>

#define FDIM 128
#define MAX_NODES 100000
#define MAX_EDGES 1600000
#define SCAN_B 1024
#define MAX_SCAN_BLOCKS ((MAX_NODES + SCAN_B - 1) / SCAN_B)

// ---------------- scratch (device globals: allocation-free rule) ----------------
__device__ __align__(16) __half g_hA[(size_t)MAX_NODES * FDIM];
__device__ __align__(16) __half g_hB[(size_t)MAX_NODES * FDIM];
__device__ float g_isq[MAX_NODES];
__device__ int   g_cnt[MAX_NODES];
__device__ int   g_lpos[MAX_EDGES];
__device__ int   g_rowptr[MAX_NODES + 1];
__device__ int   g_partial[MAX_SCAN_BLOCKS + 1];
__device__ int2  g_epack[MAX_EDGES];
__device__ __align__(16) __half g_wt1[128 * 136];
__device__ __align__(16) __half g_wt2[128 * 136];
__device__ __align__(16) __half g_wtf[64 * 136];   // fused W3@Wout, transposed
__device__ float g_bf[64];                          // fused b3@Wout + bout

// ---------------- CSR build ----------------
__global__ void zero_kernel(int* __restrict__ cnt, int n) {
    int i = blockIdx.x * blockDim.x + threadIdx.x;
    if (i < n) cnt[i] = 0;
}
__global__ void count_kernel(const int* __restrict__ dst, int* __restrict__ cnt,
                             int* __restrict__ lpos, int E) {
    int e = blockIdx.x * blockDim.x + threadIdx.x;
    if (e < E) lpos[e] = atomicAdd(&cnt[dst[e]], 1);
}
// block scan + isq fused (both read cnt)
__global__ void block_scan_kernel(const int* __restrict__ cnt, int* __restrict__ rowptr,
                                  int* __restrict__ partial, float* __restrict__ isq, int n) {
    __shared__ int sh[SCAN_B];
    int i = blockIdx.x * SCAN_B + threadIdx.x;
    int v = (i < n) ? cnt[i] : 0;
    if (i < n) isq[i] = rsqrtf((float)(v + 1));
    sh[threadIdx.x] = v;
    __syncthreads();
#pragma unroll
    for (int off = 1; off < SCAN_B; off <<= 1) {
        int t = (threadIdx.x >= off) ? sh[threadIdx.x - off] : 0;
        __syncthreads();
        sh[threadIdx.x] += t;
        __syncthreads();
    }
    if (i < n) rowptr[i] = sh[threadIdx.x] - v;
    if (threadIdx.x == SCAN_B - 1) partial[blockIdx.x] = sh[SCAN_B - 1];
}
__global__ void partial_scan_kernel(int* __restrict__ partial, int nb) {
    int lane = threadIdx.x;   // 32 threads
    int base = lane * 4;
    int v0 = (base + 0 < nb) ? partial[base + 0] : 0;
    int v1 = (base + 1 < nb) ? partial[base + 1] : 0;
    int v2 = (base + 2 < nb) ? partial[base + 2] : 0;
    int v3 = (base + 3 < nb) ? partial[base + 3] : 0;
    int tot = v0 + v1 + v2 + v3;
    int x = tot;
#pragma unroll
    for (int off = 1; off < 32; off <<= 1) {
        int y = __shfl_up_sync(0xFFFFFFFF, x, off);
        if (lane >= off) x += y;
    }
    int run = x - tot;
    if (base + 0 < nb) partial[base + 0] = run;            run += v0;
    if (base + 1 < nb) partial[base + 1] = run;            run += v1;
    if (base + 2 < nb) partial[base + 2] = run;            run += v2;
    if (base + 3 < nb) partial[base + 3] = run;
    if (lane == 31) partial[nb] = x;
}
__global__ void add_offsets_kernel(int* __restrict__ rowptr, const int* __restrict__ partial,
                                   int n, int nb) {
    int i = blockIdx.x * blockDim.x + threadIdx.x;
    if (i < n) rowptr[i] += partial[i / SCAN_B];
    if (i == 0) rowptr[n] = partial[nb];
}
__global__ void fill_kernel(const int* __restrict__ src, const int* __restrict__ dst,
                            const float* __restrict__ isq, const int* __restrict__ rowptr,
                            const int* __restrict__ lpos, int2* __restrict__ epack, int E) {
    int e = blockIdx.x * blockDim.x + threadIdx.x;
    if (e >= E) return;
    int s = src[e], d = dst[e];
    epack[rowptr[d] + lpos[e]] = make_int2(s, __float_as_int(isq[s] * isq[d]));
}

// ---------------- merged W prep: wt1, wt2, wtf=W3@Wout, bf=b3@Wout+bout ----------
__global__ void prep_all_kernel(const float* __restrict__ W1, const float* __restrict__ W2,
                                const float* __restrict__ W3, const float* __restrict__ Wo,
                                const float* __restrict__ b3, const float* __restrict__ bo,
                                __half* __restrict__ wt1, __half* __restrict__ wt2,
                                __half* __restrict__ wtf, float* __restrict__ bf) {
    int i = blockIdx.x * blockDim.x + threadIdx.x;
    if (i < 16384) {                         // wt1
        int k = i >> 7, nr = i & 127;
        wt1[nr * 136 + k] = __float2half_rn(W1[i]);
    } else if (i < 32768) {                  // wt2
        int j = i - 16384;
        int k = j >> 7, nr = j & 127;
        wt2[nr * 136 + k] = __float2half_rn(W2[j]);
    } else if (i < 32768 + 8192) {           // wtf = W3 @ Wout
        int j = i - 32768;
        int r = j >> 6, c = j & 63;
        float s = 0.f;
#pragma unroll 8
        for (int q = 0; q < 128; ++q) s += W3[r * 128 + q] * Wo[q * 64 + c];
        wtf[c * 136 + r] = __float2half_rn(s);
    } else if (i < 32768 + 8192 + 64) {      // bf
        int c = i - 32768 - 8192;
        float s = bo[c];
#pragma unroll 8
        for (int q = 0; q < 128; ++q) s += b3[q] * Wo[q * 64 + c];
        bf[c] = s;
    }
}

// ---------------- aggregation: warp per node, CSR gather (simple loop) ------------
template <bool RELU>
__global__ void agg_kernel(const __half* __restrict__ t, const int* __restrict__ rowptr,
                           const int2* __restrict__ epack, const float* __restrict__ isq,
                           const float* __restrict__ bias, __half* __restrict__ out, int n) {
    int node = (blockIdx.x * blockDim.x + threadIdx.x) >> 5;
    if (node >= n) return;
    int lane = threadIdx.x & 31;
    int beg = rowptr[node], end = rowptr[node + 1];
    float s = isq[node], c = s * s;

    uint2 raw = __ldg((const uint2*)(t + (size_t)node * FDIM) + lane);
    float2 f0 = __half22float2(*(half2*)&raw.x);
    float2 f1 = __half22float2(*(half2*)&raw.y);
    float4 acc = make_float4(c * f0.x, c * f0.y, c * f1.x, c * f1.y);

    for (int j = beg; j < end; ++j) {
        int2 p = __ldg(&epack[j]);
        float w = __int_as_float(p.y);
        uint2 r2 = __ldg((const uint2*)(t + (size_t)p.x * FDIM) + lane);
        float2 g0 = __half22float2(*(half2*)&r2.x);
        float2 g1 = __half22float2(*(half2*)&r2.y);
        acc.x += w * g0.x; acc.y += w * g0.y; acc.z += w * g1.x; acc.w += w * g1.y;
    }
    float4 b = __ldg((const float4*)bias + lane);
    acc.x += b.x; acc.y += b.y; acc.z += b.z; acc.w += b.w;
    if (RELU) {
        acc.x = fmaxf(acc.x, 0.f); acc.y = fmaxf(acc.y, 0.f);
        acc.z = fmaxf(acc.z, 0.f); acc.w = fmaxf(acc.w, 0.f);
    }
    uint2 o;
    *(half2*)&o.x = __floats2half2_rn(acc.x, acc.y);
    *(half2*)&o.y = __floats2half2_rn(acc.z, acc.w);
    ((uint2*)(out + (size_t)node * FDIM))[lane] = o;
}

// final agg: 64 features, fp32 output with fused bias (writes d_out directly)
__global__ void agg64_kernel(const __half* __restrict__ t, const int* __restrict__ rowptr,
                             const int2* __restrict__ epack, const float* __restrict__ isq,
                             const float* __restrict__ bias, float* __restrict__ out, int n) {
    int node = (blockIdx.x * blockDim.x + threadIdx.x) >> 5;
    if (node >= n) return;
    int lane = threadIdx.x & 31;
    int beg = rowptr[node], end = rowptr[node + 1];
    float s = isq[node], c = s * s;

    uint32_t raw = __ldg((const uint32_t*)(t + (size_t)node * 64) + lane);
    float2 f = __half22float2(*(half2*)&raw);
    float2 acc = make_float2(c * f.x, c * f.y);

    for (int j = beg; j < end; ++j) {
        int2 p = __ldg(&epack[j]);
        float w = __int_as_float(p.y);
        uint32_t r2 = __ldg((const uint32_t*)(t + (size_t)p.x * 64) + lane);
        float2 g = __half22float2(*(half2*)&r2);
        acc.x += w * g.x; acc.y += w * g.y;
    }
    float2 b = __ldg((const float2*)bias + lane);
    acc.x += b.x; acc.y += b.y;
    ((float2*)(out + (size_t)node * 64))[lane] = acc;
}

// ---------------- mma / ldmatrix helpers ----------------
__device__ __forceinline__ uint32_t smem_u32(const void* p) {
    uint32_t a;
    asm("{ .reg .u64 t; cvta.to.shared.u64 t, %1; cvt.u32.u64 %0, t; }" : "=r"(a) : "l"(p));
    return a;
}
__device__ __forceinline__ void mma_16n8k16(float& c0, float& c1, float& c2, float& c3,
                                            uint32_t a0, uint32_t a1, uint32_t a2, uint32_t a3,
                                            uint32_t b0, uint32_t b1) {
    asm volatile(
        "mma.sync.aligned.m16n8k16.row.col.f32.f16.f16.f32 "
        "{%0,%1,%2,%3}, {%4,%5,%6,%7}, {%8,%9}, {%0,%1,%2,%3};"
        : "+f"(c0), "+f"(c1), "+f"(c2), "+f"(c3)
        : "r"(a0), "r"(a1), "r"(a2), "r"(a3), "r"(b0), "r"(b1));
}
__device__ __forceinline__ void ldsm_x4(uint32_t& r0, uint32_t& r1, uint32_t& r2, uint32_t& r3,
                                        uint32_t addr) {
    asm volatile("ldmatrix.sync.aligned.m8n8.x4.shared.b16 {%0,%1,%2,%3}, [%4];"
                 : "=r"(r0), "=r"(r1), "=r"(r2), "=r"(r3) : "r"(addr));
}

// ---------------- GEMM: C(half) = A[M,128] @ W ; A fp32 or fp16 ------------------
// ldmatrix.x4 fragment loads: 1 for A + 4 for B per k-step (vs 20 scalar LDS).
template <int N_OUT, bool A_FP32>
__global__ __launch_bounds__(256, 3)
void gemm_mma_kernel(const void* __restrict__ Ain, const __half* __restrict__ Wimg,
                     __half* __restrict__ C, int M) {
    constexpr int COLG = N_OUT / 64;
    constexpr int ROWG = 8 / COLG;
    constexpr int BM   = ROWG * 16;
    constexpr int AST  = 136;
    constexpr int KS   = 136;
    constexpr int NT   = 8;

    extern __shared__ __half smem_h[];
    __half* As = smem_h;                    // [BM][AST]
    __half* Wt = smem_h + BM * AST;         // [N_OUT][KS]

    int tid  = threadIdx.x;
    int wid  = tid >> 5;
    int lane = tid & 31;
    int g    = lane >> 2;
    int t4   = lane & 3;
    int wid_r = wid / COLG;
    int wid_c = wid % COLG;
    int row0 = blockIdx.x * BM;

    for (int i = tid; i < N_OUT * 17; i += 256)
        ((uint4*)Wt)[i] = ((const uint4*)Wimg)[i];
    for (int i = tid; i < BM * 32; i += 256) {
        int r  = i >> 5;
        int c4 = i & 31;
        int gr = row0 + r;
        uint2 v = make_uint2(0u, 0u);
        if (gr < M) {
            if (A_FP32) {
                float4 f = ((const float4*)((const float*)Ain + (size_t)gr * FDIM))[c4];
                *(half2*)&v.x = __floats2half2_rn(f.x, f.y);
                *(half2*)&v.y = __floats2half2_rn(f.z, f.w);
            } else {
                v = ((const uint2*)((const __half*)Ain + (size_t)gr * FDIM))[c4];
            }
        }
        *(uint2*)(As + r * AST + c4 * 4) = v;
    }
    __syncthreads();

    float acc[NT][4];
#pragma unroll
    for (int nt = 0; nt < NT; ++nt) {
        acc[nt][0] = 0.f; acc[nt][1] = 0.f; acc[nt][2] = 0.f; acc[nt][3] = 0.f;
    }

    const int ncol0 = wid_c * 64;
    // A ldmatrix lane address: tiles {m0-7,k0} {m8-15,k0} {m0-7,k8} {m8-15,k8}
    // lane row = wid_r*16 + (lane&15); k offset = (lane>>4)*8
    uint32_t addrA = smem_u32(As + (wid_r * 16 + (lane & 15)) * AST + (lane >> 4) * 8);
    // B ldmatrix lane address for n-tile pair p: tiles {n0-7,k0} {n0-7,k8} {n8-15,k0} {n8-15,k8}
    // lane n = ncol0 + p*16 + ((lane>>4)&1)*8 + (lane&7); k offset = ((lane>>3)&1)*8
    uint32_t addrB0 = smem_u32(Wt + (ncol0 + ((lane >> 4) & 1) * 8 + (lane & 7)) * KS
                               + ((lane >> 3) & 1) * 8);

#pragma unroll
    for (int ks = 0; ks < 8; ++ks) {
        uint32_t a0, a1, a2, a3;
        ldsm_x4(a0, a1, a2, a3, addrA + ks * 32);          // +16 halves per k-step
#pragma unroll
        for (int p = 0; p < 4; ++p) {
            uint32_t b0, b1, b2, b3;                       // b0,b1 -> nt=2p ; b2,b3 -> nt=2p+1
            ldsm_x4(b0, b1, b2, b3, addrB0 + p * (16 * KS * 2) + ks * 32);
            mma_16n8k16(acc[2*p][0], acc[2*p][1], acc[2*p][2], acc[2*p][3],
                        a0, a1, a2, a3, b0, b1);
            mma_16n8k16(acc[2*p+1][0], acc[2*p+1][1], acc[2*p+1][2], acc[2*p+1][3],
                        a0, a1, a2, a3, b2, b3);
        }
    }

    int r_lo = row0 + wid_r * 16 + g;
    int r_hi = r_lo + 8;
#pragma unroll
    for (int nt = 0; nt < NT; ++nt) {
        int col = ncol0 + nt * 8 + 2 * t4;
        if (r_lo < M)
            *(half2*)(C + (size_t)r_lo * N_OUT + col) = __floats2half2_rn(acc[nt][0], acc[nt][1]);
        if (r_hi < M)
            *(half2*)(C + (size_t)r_hi * N_OUT + col) = __floats2half2_rn(acc[nt][2], acc[nt][3]);
    }
}

// ---------------- launch ----------------
extern "C" void kernel_launch(void* const* d_in, const int* in_sizes, int n_in,
                              void* d_out, int out_size) {
    const float* x   = (const float*)d_in[0];
    const int*   ei  = (const int*)d_in[1];     // int32 (JAX x64 disabled)
    const float* W1  = (const float*)d_in[2];
    const float* b1  = (const float*)d_in[3];
    const float* W2  = (const float*)d_in[4];
    const float* b2  = (const float*)d_in[5];
    const float* W3  = (const float*)d_in[6];
    const float* b3  = (const float*)d_in[7];
    const float* Wo  = (const float*)d_in[8];
    const float* bo  = (const float*)d_in[9];

    int n = in_sizes[0] / FDIM;
    int E = in_sizes[1] / 2;
    const int* src = ei;
    const int* dst = ei + E;

    __half *hA, *hB, *wt1, *wt2, *wtf;
    float *isq, *bf;
    int *cnt, *lpos, *rowptr, *partial;
    int2* epack;
    cudaGetSymbolAddress((void**)&hA,      g_hA);
    cudaGetSymbolAddress((void**)&hB,      g_hB);
    cudaGetSymbolAddress((void**)&isq,     g_isq);
    cudaGetSymbolAddress((void**)&cnt,     g_cnt);
    cudaGetSymbolAddress((void**)&lpos,    g_lpos);
    cudaGetSymbolAddress((void**)&rowptr,  g_rowptr);
    cudaGetSymbolAddress((void**)&partial, g_partial);
    cudaGetSymbolAddress((void**)&epack,   g_epack);
    cudaGetSymbolAddress((void**)&wt1,     g_wt1);
    cudaGetSymbolAddress((void**)&wt2,     g_wt2);
    cudaGetSymbolAddress((void**)&wtf,     g_wtf);
    cudaGetSymbolAddress((void**)&bf,      g_bf);

    const int SMEM = (64 * 136 + 128 * 136) * 2;   // 52,224 B
    cudaFuncSetAttribute(gemm_mma_kernel<128, true>,  cudaFuncAttributeMaxDynamicSharedMemorySize, SMEM);
    cudaFuncSetAttribute(gemm_mma_kernel<128, false>, cudaFuncAttributeMaxDynamicSharedMemorySize, SMEM);
    cudaFuncSetAttribute(gemm_mma_kernel<64, false>,  cudaFuncAttributeMaxDynamicSharedMemorySize, SMEM);

    const int T = 256;
    int nb_nodes   = (n + T - 1) / T;
    int nb_edges   = (E + T - 1) / T;
    int nb_agg     = (int)(((long long)n * 32 + T - 1) / T);
    int nb_gemm128 = (n + 63) / 64;
    int nb_gemm64  = (n + 127) / 128;
    int nb_scan    = (n + SCAN_B - 1) / SCAN_B;

    // gemm1 kept in the profiler capture window (slot 4); deps preserved.
    prep_all_kernel<<<(41024 + T - 1) / T, T>>>(W1, W2, W3, Wo, b3, bo, wt1, wt2, wtf, bf); // 1
    zero_kernel<<<nb_nodes, T>>>(cnt, n);                                                   // 2
    count_kernel<<<nb_edges, T>>>(dst, cnt, lpos, E);                                       // 3
    gemm_mma_kernel<128, true><<<nb_gemm128, 256, SMEM>>>(x, wt1, hA, n);                   // 4
    block_scan_kernel<<<nb_scan, SCAN_B>>>(cnt, rowptr, partial, isq, n);                   // 5
    partial_scan_kernel<<<1, 32>>>(partial, nb_scan);                                       // 6
    add_offsets_kernel<<<nb_nodes, T>>>(rowptr, partial, n, nb_scan);                       // 7
    fill_kernel<<<nb_edges, T>>>(src, dst, isq, rowptr, lpos, epack, E);                    // 8

    // ---- layer 1 agg: h1 = relu(agg(x@W1) + b1) ----
    agg_kernel<true><<<nb_agg, T>>>(hA, rowptr, epack, isq, b1, hB, n);                     // 9
    // ---- layer 2 ----
    gemm_mma_kernel<128, false><<<nb_gemm128, 256, SMEM>>>(hB, wt2, hA, n);                 // 10
    agg_kernel<true><<<nb_agg, T>>>(hA, rowptr, epack, isq, b2, hB, n);                     // 11
    // ---- layer 3 + output fused ----
    gemm_mma_kernel<64, false><<<nb_gemm64, 256, SMEM>>>(hB, wtf, hA, n);                   // 12
    agg64_kernel<<<nb_agg, T>>>(hA, rowptr, epack, isq, bf, (float*)d_out, n);              // 13
}

// round 14
// speedup vs baseline: 1.2029x; 1.1355x over previous
#include <cuda_runtime.h>
#include <cuda_fp16.h>
#include <cstdint>

#define FDIM 128
#define MAX_NODES 100000
#define MAX_EDGES 1600000
#define SCAN_B 1024
#define MAX_SCAN_BLOCKS ((MAX_NODES + SCAN_B - 1) / SCAN_B)

// ---------------- scratch (device globals: allocation-free rule) ----------------
__device__ __align__(16) __half g_hA[(size_t)MAX_NODES * FDIM];
__device__ __align__(16) __half g_hB[(size_t)MAX_NODES * FDIM];
__device__ float g_isq[MAX_NODES];
__device__ int   g_cnt[MAX_NODES];
__device__ int   g_lpos[MAX_EDGES];
__device__ int   g_rowptr[MAX_NODES + 1];
__device__ int   g_partial[MAX_SCAN_BLOCKS + 1];
__device__ int2  g_epack[MAX_EDGES];
__device__ __align__(16) __half g_wt1[128 * 136];
__device__ __align__(16) __half g_wt2[128 * 136];
__device__ __align__(16) __half g_wtf[64 * 136];   // fused W3@Wout, transposed
__device__ float g_bf[64];                          // fused b3@Wout + bout

// ---------------- CSR build ----------------
__global__ void zero_kernel(int* __restrict__ cnt, int n) {
    int i = blockIdx.x * blockDim.x + threadIdx.x;
    if (i < n) cnt[i] = 0;
}
__global__ void count_kernel(const int* __restrict__ dst, int* __restrict__ cnt,
                             int* __restrict__ lpos, int E) {
    int e = blockIdx.x * blockDim.x + threadIdx.x;
    if (e < E) lpos[e] = atomicAdd(&cnt[dst[e]], 1);
}
// block scan + isq fused (both read cnt)
__global__ void block_scan_kernel(const int* __restrict__ cnt, int* __restrict__ rowptr,
                                  int* __restrict__ partial, float* __restrict__ isq, int n) {
    __shared__ int sh[SCAN_B];
    int i = blockIdx.x * SCAN_B + threadIdx.x;
    int v = (i < n) ? cnt[i] : 0;
    if (i < n) isq[i] = rsqrtf((float)(v + 1));
    sh[threadIdx.x] = v;
    __syncthreads();
#pragma unroll
    for (int off = 1; off < SCAN_B; off <<= 1) {
        int t = (threadIdx.x >= off) ? sh[threadIdx.x - off] : 0;
        __syncthreads();
        sh[threadIdx.x] += t;
        __syncthreads();
    }
    if (i < n) rowptr[i] = sh[threadIdx.x] - v;
    if (threadIdx.x == SCAN_B - 1) partial[blockIdx.x] = sh[SCAN_B - 1];
}
__global__ void partial_scan_kernel(int* __restrict__ partial, int nb) {
    int lane = threadIdx.x;   // 32 threads
    int base = lane * 4;
    int v0 = (base + 0 < nb) ? partial[base + 0] : 0;
    int v1 = (base + 1 < nb) ? partial[base + 1] : 0;
    int v2 = (base + 2 < nb) ? partial[base + 2] : 0;
    int v3 = (base + 3 < nb) ? partial[base + 3] : 0;
    int tot = v0 + v1 + v2 + v3;
    int x = tot;
#pragma unroll
    for (int off = 1; off < 32; off <<= 1) {
        int y = __shfl_up_sync(0xFFFFFFFF, x, off);
        if (lane >= off) x += y;
    }
    int run = x - tot;
    if (base + 0 < nb) partial[base + 0] = run;            run += v0;
    if (base + 1 < nb) partial[base + 1] = run;            run += v1;
    if (base + 2 < nb) partial[base + 2] = run;            run += v2;
    if (base + 3 < nb) partial[base + 3] = run;
    if (lane == 31) partial[nb] = x;
}
__global__ void add_offsets_kernel(int* __restrict__ rowptr, const int* __restrict__ partial,
                                   int n, int nb) {
    int i = blockIdx.x * blockDim.x + threadIdx.x;
    if (i < n) rowptr[i] += partial[i / SCAN_B];
    if (i == 0) rowptr[n] = partial[nb];
}
__global__ void fill_kernel(const int* __restrict__ src, const int* __restrict__ dst,
                            const float* __restrict__ isq, const int* __restrict__ rowptr,
                            const int* __restrict__ lpos, int2* __restrict__ epack, int E) {
    int e = blockIdx.x * blockDim.x + threadIdx.x;
    if (e >= E) return;
    int s = src[e], d = dst[e];
    epack[rowptr[d] + lpos[e]] = make_int2(s, __float_as_int(isq[s] * isq[d]));
}

// ---------------- merged W prep: wt1, wt2, wtf=W3@Wout, bf=b3@Wout+bout ----------
__global__ void prep_all_kernel(const float* __restrict__ W1, const float* __restrict__ W2,
                                const float* __restrict__ W3, const float* __restrict__ Wo,
                                const float* __restrict__ b3, const float* __restrict__ bo,
                                __half* __restrict__ wt1, __half* __restrict__ wt2,
                                __half* __restrict__ wtf, float* __restrict__ bf) {
    int i = blockIdx.x * blockDim.x + threadIdx.x;
    if (i < 16384) {                         // wt1
        int k = i >> 7, nr = i & 127;
        wt1[nr * 136 + k] = __float2half_rn(W1[i]);
    } else if (i < 32768) {                  // wt2
        int j = i - 16384;
        int k = j >> 7, nr = j & 127;
        wt2[nr * 136 + k] = __float2half_rn(W2[j]);
    } else if (i < 32768 + 8192) {           // wtf = W3 @ Wout
        int j = i - 32768;
        int r = j >> 6, c = j & 63;
        float s = 0.f;
#pragma unroll 8
        for (int q = 0; q < 128; ++q) s += W3[r * 128 + q] * Wo[q * 64 + c];
        wtf[c * 136 + r] = __float2half_rn(s);
    } else if (i < 32768 + 8192 + 64) {      // bf
        int c = i - 32768 - 8192;
        float s = bo[c];
#pragma unroll 8
        for (int q = 0; q < 128; ++q) s += b3[q] * Wo[q * 64 + c];
        bf[c] = s;
    }
}

// ---------------- aggregation: warp per node, CSR gather (simple loop) ------------
template <bool RELU>
__global__ void agg_kernel(const __half* __restrict__ t, const int* __restrict__ rowptr,
                           const int2* __restrict__ epack, const float* __restrict__ isq,
                           const float* __restrict__ bias, __half* __restrict__ out, int n) {
    int node = (blockIdx.x * blockDim.x + threadIdx.x) >> 5;
    if (node >= n) return;
    int lane = threadIdx.x & 31;
    int beg = rowptr[node], end = rowptr[node + 1];
    float s = isq[node], c = s * s;

    uint2 raw = __ldg((const uint2*)(t + (size_t)node * FDIM) + lane);
    float2 f0 = __half22float2(*(half2*)&raw.x);
    float2 f1 = __half22float2(*(half2*)&raw.y);
    float4 acc = make_float4(c * f0.x, c * f0.y, c * f1.x, c * f1.y);

    for (int j = beg; j < end; ++j) {
        int2 p = __ldg(&epack[j]);
        float w = __int_as_float(p.y);
        uint2 r2 = __ldg((const uint2*)(t + (size_t)p.x * FDIM) + lane);
        float2 g0 = __half22float2(*(half2*)&r2.x);
        float2 g1 = __half22float2(*(half2*)&r2.y);
        acc.x += w * g0.x; acc.y += w * g0.y; acc.z += w * g1.x; acc.w += w * g1.y;
    }
    float4 b = __ldg((const float4*)bias + lane);
    acc.x += b.x; acc.y += b.y; acc.z += b.z; acc.w += b.w;
    if (RELU) {
        acc.x = fmaxf(acc.x, 0.f); acc.y = fmaxf(acc.y, 0.f);
        acc.z = fmaxf(acc.z, 0.f); acc.w = fmaxf(acc.w, 0.f);
    }
    uint2 o;
    *(half2*)&o.x = __floats2half2_rn(acc.x, acc.y);
    *(half2*)&o.y = __floats2half2_rn(acc.z, acc.w);
    ((uint2*)(out + (size_t)node * FDIM))[lane] = o;
}

// final agg: 64 features, fp32 output with fused bias (writes d_out directly)
__global__ void agg64_kernel(const __half* __restrict__ t, const int* __restrict__ rowptr,
                             const int2* __restrict__ epack, const float* __restrict__ isq,
                             const float* __restrict__ bias, float* __restrict__ out, int n) {
    int node = (blockIdx.x * blockDim.x + threadIdx.x) >> 5;
    if (node >= n) return;
    int lane = threadIdx.x & 31;
    int beg = rowptr[node], end = rowptr[node + 1];
    float s = isq[node], c = s * s;

    uint32_t raw = __ldg((const uint32_t*)(t + (size_t)node * 64) + lane);
    float2 f = __half22float2(*(half2*)&raw);
    float2 acc = make_float2(c * f.x, c * f.y);

    for (int j = beg; j < end; ++j) {
        int2 p = __ldg(&epack[j]);
        float w = __int_as_float(p.y);
        uint32_t r2 = __ldg((const uint32_t*)(t + (size_t)p.x * 64) + lane);
        float2 g = __half22float2(*(half2*)&r2);
        acc.x += w * g.x; acc.y += w * g.y;
    }
    float2 b = __ldg((const float2*)bias + lane);
    acc.x += b.x; acc.y += b.y;
    ((float2*)(out + (size_t)node * 64))[lane] = acc;
}

// ---------------- fp16 mma helper ----------------
__device__ __forceinline__ void mma_16n8k16(float& c0, float& c1, float& c2, float& c3,
                                            uint32_t a0, uint32_t a1, uint32_t a2, uint32_t a3,
                                            uint32_t b0, uint32_t b1) {
    asm volatile(
        "mma.sync.aligned.m16n8k16.row.col.f32.f16.f16.f32 "
        "{%0,%1,%2,%3}, {%4,%5,%6,%7}, {%8,%9}, {%0,%1,%2,%3};"
        : "+f"(c0), "+f"(c1), "+f"(c2), "+f"(c3)
        : "r"(a0), "r"(a1), "r"(a2), "r"(a3), "r"(b0), "r"(b1));
}

// ---------------- persistent GEMM: C(half) = A[M,128] @ W -------------------------
// W staged ONCE per block; grid-stride loop over row tiles (amortizes W traffic).
// Scalar-LDS fragment loads (R11 mainloop — best measured config: regs 63, 4 CTA/SM).
template <int N_OUT, bool A_FP32>
__global__ __launch_bounds__(256, 4)
void gemm_mma_kernel(const void* __restrict__ Ain, const __half* __restrict__ Wimg,
                     __half* __restrict__ C, int M, int ntiles) {
    constexpr int COLG = N_OUT / 64;
    constexpr int ROWG = 8 / COLG;
    constexpr int BM   = ROWG * 16;
    constexpr int AST  = 136;
    constexpr int KS   = 136;
    constexpr int NT   = 8;

    extern __shared__ __half smem_h[];
    __half* As = smem_h;                    // [BM][AST]
    __half* Wt = smem_h + BM * AST;         // [N_OUT][KS]

    int tid  = threadIdx.x;
    int wid  = tid >> 5;
    int lane = tid & 31;
    int g    = lane >> 2;
    int t4   = lane & 3;
    int wid_r = wid / COLG;
    int wid_c = wid % COLG;
    const int ncol0 = wid_c * 64;

    // stage W once per block
    for (int i = tid; i < N_OUT * 17; i += 256)
        ((uint4*)Wt)[i] = ((const uint4*)Wimg)[i];

    for (int tile = blockIdx.x; tile < ntiles; tile += gridDim.x) {
        int row0 = tile * BM;

        __syncthreads();   // W ready (1st iter); prior compute done before As overwrite
        for (int i = tid; i < BM * 32; i += 256) {
            int r  = i >> 5;
            int c4 = i & 31;
            int gr = row0 + r;
            uint2 v = make_uint2(0u, 0u);
            if (gr < M) {
                if (A_FP32) {
                    float4 f = ((const float4*)((const float*)Ain + (size_t)gr * FDIM))[c4];
                    *(half2*)&v.x = __floats2half2_rn(f.x, f.y);
                    *(half2*)&v.y = __floats2half2_rn(f.z, f.w);
                } else {
                    v = ((const uint2*)((const __half*)Ain + (size_t)gr * FDIM))[c4];
                }
            }
            *(uint2*)(As + r * AST + c4 * 4) = v;
        }
        __syncthreads();

        float acc[NT][4];
#pragma unroll
        for (int nt = 0; nt < NT; ++nt) {
            acc[nt][0] = 0.f; acc[nt][1] = 0.f; acc[nt][2] = 0.f; acc[nt][3] = 0.f;
        }

        const __half* arow_lo = As + (wid_r * 16 + g) * AST;
        const __half* arow_hi = arow_lo + 8 * AST;

#pragma unroll
        for (int ks = 0; ks < 8; ++ks) {
            int k0 = ks * 16 + 2 * t4;
            uint32_t a0 = *(const uint32_t*)(arow_lo + k0);
            uint32_t a1 = *(const uint32_t*)(arow_hi + k0);
            uint32_t a2 = *(const uint32_t*)(arow_lo + k0 + 8);
            uint32_t a3 = *(const uint32_t*)(arow_hi + k0 + 8);
            const __half* wb = Wt + (ncol0 + g) * KS + k0;
#pragma unroll
            for (int nt = 0; nt < NT; ++nt) {
                uint32_t b0 = *(const uint32_t*)(wb + nt * 8 * KS);
                uint32_t b1 = *(const uint32_t*)(wb + nt * 8 * KS + 8);
                mma_16n8k16(acc[nt][0], acc[nt][1], acc[nt][2], acc[nt][3],
                            a0, a1, a2, a3, b0, b1);
            }
        }

        int r_lo = row0 + wid_r * 16 + g;
        int r_hi = r_lo + 8;
#pragma unroll
        for (int nt = 0; nt < NT; ++nt) {
            int col = ncol0 + nt * 8 + 2 * t4;
            if (r_lo < M)
                *(half2*)(C + (size_t)r_lo * N_OUT + col) = __floats2half2_rn(acc[nt][0], acc[nt][1]);
            if (r_hi < M)
                *(half2*)(C + (size_t)r_hi * N_OUT + col) = __floats2half2_rn(acc[nt][2], acc[nt][3]);
        }
    }
}

// ---------------- launch ----------------
extern "C" void kernel_launch(void* const* d_in, const int* in_sizes, int n_in,
                              void* d_out, int out_size) {
    const float* x   = (const float*)d_in[0];
    const int*   ei  = (const int*)d_in[1];     // int32 (JAX x64 disabled)
    const float* W1  = (const float*)d_in[2];
    const float* b1  = (const float*)d_in[3];
    const float* W2  = (const float*)d_in[4];
    const float* b2  = (const float*)d_in[5];
    const float* W3  = (const float*)d_in[6];
    const float* b3  = (const float*)d_in[7];
    const float* Wo  = (const float*)d_in[8];
    const float* bo  = (const float*)d_in[9];

    int n = in_sizes[0] / FDIM;
    int E = in_sizes[1] / 2;
    const int* src = ei;
    const int* dst = ei + E;

    __half *hA, *hB, *wt1, *wt2, *wtf;
    float *isq, *bf;
    int *cnt, *lpos, *rowptr, *partial;
    int2* epack;
    cudaGetSymbolAddress((void**)&hA,      g_hA);
    cudaGetSymbolAddress((void**)&hB,      g_hB);
    cudaGetSymbolAddress((void**)&isq,     g_isq);
    cudaGetSymbolAddress((void**)&cnt,     g_cnt);
    cudaGetSymbolAddress((void**)&lpos,    g_lpos);
    cudaGetSymbolAddress((void**)&rowptr,  g_rowptr);
    cudaGetSymbolAddress((void**)&partial, g_partial);
    cudaGetSymbolAddress((void**)&epack,   g_epack);
    cudaGetSymbolAddress((void**)&wt1,     g_wt1);
    cudaGetSymbolAddress((void**)&wt2,     g_wt2);
    cudaGetSymbolAddress((void**)&wtf,     g_wtf);
    cudaGetSymbolAddress((void**)&bf,      g_bf);

    const int SMEM = (64 * 136 + 128 * 136) * 2;   // 52,224 B
    cudaFuncSetAttribute(gemm_mma_kernel<128, true>,  cudaFuncAttributeMaxDynamicSharedMemorySize, SMEM);
    cudaFuncSetAttribute(gemm_mma_kernel<128, false>, cudaFuncAttributeMaxDynamicSharedMemorySize, SMEM);
    cudaFuncSetAttribute(gemm_mma_kernel<64, false>,  cudaFuncAttributeMaxDynamicSharedMemorySize, SMEM);

    const int T = 256;
    int nb_nodes   = (n + T - 1) / T;
    int nb_edges   = (E + T - 1) / T;
    int nb_agg     = (int)(((long long)n * 32 + T - 1) / T);
    int nt128      = (n + 63) / 64;      // row tiles for N_OUT=128 (BM=64)
    int nt64       = (n + 127) / 128;    // row tiles for N_OUT=64  (BM=128)
    int nb_scan    = (n + SCAN_B - 1) / SCAN_B;
    const int PERSIST = 148 * 4;         // 4 CTAs/SM persistent grid
    int gb128 = nt128 < PERSIST ? nt128 : PERSIST;
    int gb64  = nt64  < PERSIST ? nt64  : PERSIST;

    // gemm1 kept in the profiler capture window (slot 4); deps preserved.
    prep_all_kernel<<<(41024 + T - 1) / T, T>>>(W1, W2, W3, Wo, b3, bo, wt1, wt2, wtf, bf); // 1
    zero_kernel<<<nb_nodes, T>>>(cnt, n);                                                   // 2
    count_kernel<<<nb_edges, T>>>(dst, cnt, lpos, E);                                       // 3
    gemm_mma_kernel<128, true><<<gb128, 256, SMEM>>>(x, wt1, hA, n, nt128);                 // 4
    block_scan_kernel<<<nb_scan, SCAN_B>>>(cnt, rowptr, partial, isq, n);                   // 5
    partial_scan_kernel<<<1, 32>>>(partial, nb_scan);                                       // 6
    add_offsets_kernel<<<nb_nodes, T>>>(rowptr, partial, n, nb_scan);                       // 7
    fill_kernel<<<nb_edges, T>>>(src, dst, isq, rowptr, lpos, epack, E);                    // 8

    // ---- layer 1 agg: h1 = relu(agg(x@W1) + b1) ----
    agg_kernel<true><<<nb_agg, T>>>(hA, rowptr, epack, isq, b1, hB, n);                     // 9
    // ---- layer 2 ----
    gemm_mma_kernel<128, false><<<gb128, 256, SMEM>>>(hB, wt2, hA, n, nt128);               // 10
    agg_kernel<true><<<nb_agg, T>>>(hA, rowptr, epack, isq, b2, hB, n);                     // 11
    // ---- layer 3 + output fused ----
    gemm_mma_kernel<64, false><<<gb64, 256, SMEM>>>(hB, wtf, hA, n, nt64);                  // 12
    agg64_kernel<<<nb_agg, T>>>(hA, rowptr, epack, isq, bf, (float*)d_out, n);              // 13
}

// round 15
// speedup vs baseline: 1.2142x; 1.0094x over previous
#include <cuda_runtime.h>
#include <cuda_fp16.h>
#include <cstdint>

#define FDIM 128
#define MAX_NODES 100000
#define MAX_EDGES 1600000
#define SCAN_B 1024
#define MAX_SCAN_BLOCKS ((MAX_NODES + SCAN_B - 1) / SCAN_B)

// ---------------- scratch (device globals: allocation-free rule) ----------------
__device__ __align__(16) __half g_hA[(size_t)MAX_NODES * FDIM];
__device__ __align__(16) __half g_hB[(size_t)MAX_NODES * FDIM];
__device__ float g_isq[MAX_NODES];
__device__ int   g_cnt[MAX_NODES];
__device__ int   g_lpos[MAX_EDGES];
__device__ int   g_rowptr[MAX_NODES + 1];
__device__ int   g_partial[MAX_SCAN_BLOCKS + 1];
__device__ int2  g_epack[MAX_EDGES];
__device__ __align__(16) __half g_wt1[128 * 136];
__device__ __align__(16) __half g_wt2[128 * 136];
__device__ __align__(16) __half g_wtf[64 * 136];   // fused W3@Wout, transposed
__device__ float g_bf[64];                          // fused b3@Wout + bout

// ---------------- CSR build ----------------
__global__ void zero_kernel(int* __restrict__ cnt, int n) {
    int i = blockIdx.x * blockDim.x + threadIdx.x;
    if (i < n) cnt[i] = 0;
}
__global__ void count_kernel(const int* __restrict__ dst, int* __restrict__ cnt,
                             int* __restrict__ lpos, int E) {
    int e = blockIdx.x * blockDim.x + threadIdx.x;
    if (e < E) lpos[e] = atomicAdd(&cnt[dst[e]], 1);
}
// block scan + isq fused (both read cnt)
__global__ void block_scan_kernel(const int* __restrict__ cnt, int* __restrict__ rowptr,
                                  int* __restrict__ partial, float* __restrict__ isq, int n) {
    __shared__ int sh[SCAN_B];
    int i = blockIdx.x * SCAN_B + threadIdx.x;
    int v = (i < n) ? cnt[i] : 0;
    if (i < n) isq[i] = rsqrtf((float)(v + 1));
    sh[threadIdx.x] = v;
    __syncthreads();
#pragma unroll
    for (int off = 1; off < SCAN_B; off <<= 1) {
        int t = (threadIdx.x >= off) ? sh[threadIdx.x - off] : 0;
        __syncthreads();
        sh[threadIdx.x] += t;
        __syncthreads();
    }
    if (i < n) rowptr[i] = sh[threadIdx.x] - v;
    if (threadIdx.x == SCAN_B - 1) partial[blockIdx.x] = sh[SCAN_B - 1];
}
__global__ void partial_scan_kernel(int* __restrict__ partial, int nb) {
    int lane = threadIdx.x;   // 32 threads
    int base = lane * 4;
    int v0 = (base + 0 < nb) ? partial[base + 0] : 0;
    int v1 = (base + 1 < nb) ? partial[base + 1] : 0;
    int v2 = (base + 2 < nb) ? partial[base + 2] : 0;
    int v3 = (base + 3 < nb) ? partial[base + 3] : 0;
    int tot = v0 + v1 + v2 + v3;
    int x = tot;
#pragma unroll
    for (int off = 1; off < 32; off <<= 1) {
        int y = __shfl_up_sync(0xFFFFFFFF, x, off);
        if (lane >= off) x += y;
    }
    int run = x - tot;
    if (base + 0 < nb) partial[base + 0] = run;            run += v0;
    if (base + 1 < nb) partial[base + 1] = run;            run += v1;
    if (base + 2 < nb) partial[base + 2] = run;            run += v2;
    if (base + 3 < nb) partial[base + 3] = run;
    if (lane == 31) partial[nb] = x;
}
__global__ void add_offsets_kernel(int* __restrict__ rowptr, const int* __restrict__ partial,
                                   int n, int nb) {
    int i = blockIdx.x * blockDim.x + threadIdx.x;
    if (i < n) rowptr[i] += partial[i / SCAN_B];
    if (i == 0) rowptr[n] = partial[nb];
}
__global__ void fill_kernel(const int* __restrict__ src, const int* __restrict__ dst,
                            const float* __restrict__ isq, const int* __restrict__ rowptr,
                            const int* __restrict__ lpos, int2* __restrict__ epack, int E) {
    int e = blockIdx.x * blockDim.x + threadIdx.x;
    if (e >= E) return;
    int s = src[e], d = dst[e];
    epack[rowptr[d] + lpos[e]] = make_int2(s, __float_as_int(isq[s] * isq[d]));
}

// ---------------- merged W prep: wt1, wt2, wtf=W3@Wout, bf=b3@Wout+bout ----------
__global__ void prep_all_kernel(const float* __restrict__ W1, const float* __restrict__ W2,
                                const float* __restrict__ W3, const float* __restrict__ Wo,
                                const float* __restrict__ b3, const float* __restrict__ bo,
                                __half* __restrict__ wt1, __half* __restrict__ wt2,
                                __half* __restrict__ wtf, float* __restrict__ bf) {
    int i = blockIdx.x * blockDim.x + threadIdx.x;
    if (i < 16384) {                         // wt1
        int k = i >> 7, nr = i & 127;
        wt1[nr * 136 + k] = __float2half_rn(W1[i]);
    } else if (i < 32768) {                  // wt2
        int j = i - 16384;
        int k = j >> 7, nr = j & 127;
        wt2[nr * 136 + k] = __float2half_rn(W2[j]);
    } else if (i < 32768 + 8192) {           // wtf = W3 @ Wout
        int j = i - 32768;
        int r = j >> 6, c = j & 63;
        float s = 0.f;
#pragma unroll 8
        for (int q = 0; q < 128; ++q) s += W3[r * 128 + q] * Wo[q * 64 + c];
        wtf[c * 136 + r] = __float2half_rn(s);
    } else if (i < 32768 + 8192 + 64) {      // bf
        int c = i - 32768 - 8192;
        float s = bo[c];
#pragma unroll 8
        for (int q = 0; q < 128; ++q) s += b3[q] * Wo[q * 64 + c];
        bf[c] = s;
    }
}

// ---------------- aggregation: warp per node, CSR gather (simple loop) ------------
template <bool RELU>
__global__ void agg_kernel(const __half* __restrict__ t, const int* __restrict__ rowptr,
                           const int2* __restrict__ epack, const float* __restrict__ isq,
                           const float* __restrict__ bias, __half* __restrict__ out, int n) {
    int node = (blockIdx.x * blockDim.x + threadIdx.x) >> 5;
    if (node >= n) return;
    int lane = threadIdx.x & 31;
    int beg = rowptr[node], end = rowptr[node + 1];
    float s = isq[node], c = s * s;

    uint2 raw = __ldg((const uint2*)(t + (size_t)node * FDIM) + lane);
    float2 f0 = __half22float2(*(half2*)&raw.x);
    float2 f1 = __half22float2(*(half2*)&raw.y);
    float4 acc = make_float4(c * f0.x, c * f0.y, c * f1.x, c * f1.y);

    for (int j = beg; j < end; ++j) {
        int2 p = __ldg(&epack[j]);
        float w = __int_as_float(p.y);
        uint2 r2 = __ldg((const uint2*)(t + (size_t)p.x * FDIM) + lane);
        float2 g0 = __half22float2(*(half2*)&r2.x);
        float2 g1 = __half22float2(*(half2*)&r2.y);
        acc.x += w * g0.x; acc.y += w * g0.y; acc.z += w * g1.x; acc.w += w * g1.y;
    }
    float4 b = __ldg((const float4*)bias + lane);
    acc.x += b.x; acc.y += b.y; acc.z += b.z; acc.w += b.w;
    if (RELU) {
        acc.x = fmaxf(acc.x, 0.f); acc.y = fmaxf(acc.y, 0.f);
        acc.z = fmaxf(acc.z, 0.f); acc.w = fmaxf(acc.w, 0.f);
    }
    uint2 o;
    *(half2*)&o.x = __floats2half2_rn(acc.x, acc.y);
    *(half2*)&o.y = __floats2half2_rn(acc.z, acc.w);
    ((uint2*)(out + (size_t)node * FDIM))[lane] = o;
}

// final agg: 64 features, fp32 output with fused bias (writes d_out directly)
__global__ void agg64_kernel(const __half* __restrict__ t, const int* __restrict__ rowptr,
                             const int2* __restrict__ epack, const float* __restrict__ isq,
                             const float* __restrict__ bias, float* __restrict__ out, int n) {
    int node = (blockIdx.x * blockDim.x + threadIdx.x) >> 5;
    if (node >= n) return;
    int lane = threadIdx.x & 31;
    int beg = rowptr[node], end = rowptr[node + 1];
    float s = isq[node], c = s * s;

    uint32_t raw = __ldg((const uint32_t*)(t + (size_t)node * 64) + lane);
    float2 f = __half22float2(*(half2*)&raw);
    float2 acc = make_float2(c * f.x, c * f.y);

    for (int j = beg; j < end; ++j) {
        int2 p = __ldg(&epack[j]);
        float w = __int_as_float(p.y);
        uint32_t r2 = __ldg((const uint32_t*)(t + (size_t)p.x * 64) + lane);
        float2 g = __half22float2(*(half2*)&r2);
        acc.x += w * g.x; acc.y += w * g.y;
    }
    float2 b = __ldg((const float2*)bias + lane);
    acc.x += b.x; acc.y += b.y;
    ((float2*)(out + (size_t)node * 64))[lane] = acc;
}

// ---------------- fp16 mma helper ----------------
__device__ __forceinline__ void mma_16n8k16(float& c0, float& c1, float& c2, float& c3,
                                            uint32_t a0, uint32_t a1, uint32_t a2, uint32_t a3,
                                            uint32_t b0, uint32_t b1) {
    asm volatile(
        "mma.sync.aligned.m16n8k16.row.col.f32.f16.f16.f32 "
        "{%0,%1,%2,%3}, {%4,%5,%6,%7}, {%8,%9}, {%0,%1,%2,%3};"
        : "+f"(c0), "+f"(c1), "+f"(c2), "+f"(c3)
        : "r"(a0), "r"(a1), "r"(a2), "r"(a3), "r"(b0), "r"(b1));
}

// ---------------- persistent GEMM: C(half) = A[M,128] @ W -------------------------
// W staged ONCE per block; grid-stride loop over row tiles (amortizes W traffic).
template <int N_OUT, bool A_FP32>
__global__ __launch_bounds__(256, 4)
void gemm_mma_kernel(const void* __restrict__ Ain, const __half* __restrict__ Wimg,
                     __half* __restrict__ C, int M, int ntiles) {
    constexpr int COLG = N_OUT / 64;
    constexpr int ROWG = 8 / COLG;
    constexpr int BM   = ROWG * 16;
    constexpr int AST  = 136;
    constexpr int KS   = 136;
    constexpr int NT   = 8;

    extern __shared__ __half smem_h[];
    __half* As = smem_h;                    // [BM][AST]
    __half* Wt = smem_h + BM * AST;         // [N_OUT][KS]

    int tid  = threadIdx.x;
    int wid  = tid >> 5;
    int lane = tid & 31;
    int g    = lane >> 2;
    int t4   = lane & 3;
    int wid_r = wid / COLG;
    int wid_c = wid % COLG;
    const int ncol0 = wid_c * 64;

    // stage W once per block
    for (int i = tid; i < N_OUT * 17; i += 256)
        ((uint4*)Wt)[i] = ((const uint4*)Wimg)[i];

    for (int tile = blockIdx.x; tile < ntiles; tile += gridDim.x) {
        int row0 = tile * BM;

        __syncthreads();   // W ready (1st iter); prior compute done before As overwrite
        for (int i = tid; i < BM * 32; i += 256) {
            int r  = i >> 5;
            int c4 = i & 31;
            int gr = row0 + r;
            uint2 v = make_uint2(0u, 0u);
            if (gr < M) {
                if (A_FP32) {
                    float4 f = ((const float4*)((const float*)Ain + (size_t)gr * FDIM))[c4];
                    *(half2*)&v.x = __floats2half2_rn(f.x, f.y);
                    *(half2*)&v.y = __floats2half2_rn(f.z, f.w);
                } else {
                    v = ((const uint2*)((const __half*)Ain + (size_t)gr * FDIM))[c4];
                }
            }
            *(uint2*)(As + r * AST + c4 * 4) = v;
        }
        __syncthreads();

        float acc[NT][4];
#pragma unroll
        for (int nt = 0; nt < NT; ++nt) {
            acc[nt][0] = 0.f; acc[nt][1] = 0.f; acc[nt][2] = 0.f; acc[nt][3] = 0.f;
        }

        const __half* arow_lo = As + (wid_r * 16 + g) * AST;
        const __half* arow_hi = arow_lo + 8 * AST;

#pragma unroll
        for (int ks = 0; ks < 8; ++ks) {
            int k0 = ks * 16 + 2 * t4;
            uint32_t a0 = *(const uint32_t*)(arow_lo + k0);
            uint32_t a1 = *(const uint32_t*)(arow_hi + k0);
            uint32_t a2 = *(const uint32_t*)(arow_lo + k0 + 8);
            uint32_t a3 = *(const uint32_t*)(arow_hi + k0 + 8);
            const __half* wb = Wt + (ncol0 + g) * KS + k0;
#pragma unroll
            for (int nt = 0; nt < NT; ++nt) {
                uint32_t b0 = *(const uint32_t*)(wb + nt * 8 * KS);
                uint32_t b1 = *(const uint32_t*)(wb + nt * 8 * KS + 8);
                mma_16n8k16(acc[nt][0], acc[nt][1], acc[nt][2], acc[nt][3],
                            a0, a1, a2, a3, b0, b1);
            }
        }

        int r_lo = row0 + wid_r * 16 + g;
        int r_hi = r_lo + 8;
#pragma unroll
        for (int nt = 0; nt < NT; ++nt) {
            int col = ncol0 + nt * 8 + 2 * t4;
            if (r_lo < M)
                *(half2*)(C + (size_t)r_lo * N_OUT + col) = __floats2half2_rn(acc[nt][0], acc[nt][1]);
            if (r_hi < M)
                *(half2*)(C + (size_t)r_hi * N_OUT + col) = __floats2half2_rn(acc[nt][2], acc[nt][3]);
        }
    }
}

// ---------------- launch ----------------
extern "C" void kernel_launch(void* const* d_in, const int* in_sizes, int n_in,
                              void* d_out, int out_size) {
    const float* x   = (const float*)d_in[0];
    const int*   ei  = (const int*)d_in[1];     // int32 (JAX x64 disabled)
    const float* W1  = (const float*)d_in[2];
    const float* b1  = (const float*)d_in[3];
    const float* W2  = (const float*)d_in[4];
    const float* b2  = (const float*)d_in[5];
    const float* W3  = (const float*)d_in[6];
    const float* b3  = (const float*)d_in[7];
    const float* Wo  = (const float*)d_in[8];
    const float* bo  = (const float*)d_in[9];

    int n = in_sizes[0] / FDIM;
    int E = in_sizes[1] / 2;
    const int* src = ei;
    const int* dst = ei + E;

    __half *hA, *hB, *wt1, *wt2, *wtf;
    float *isq, *bf;
    int *cnt, *lpos, *rowptr, *partial;
    int2* epack;
    cudaGetSymbolAddress((void**)&hA,      g_hA);
    cudaGetSymbolAddress((void**)&hB,      g_hB);
    cudaGetSymbolAddress((void**)&isq,     g_isq);
    cudaGetSymbolAddress((void**)&cnt,     g_cnt);
    cudaGetSymbolAddress((void**)&lpos,    g_lpos);
    cudaGetSymbolAddress((void**)&rowptr,  g_rowptr);
    cudaGetSymbolAddress((void**)&partial, g_partial);
    cudaGetSymbolAddress((void**)&epack,   g_epack);
    cudaGetSymbolAddress((void**)&wt1,     g_wt1);
    cudaGetSymbolAddress((void**)&wt2,     g_wt2);
    cudaGetSymbolAddress((void**)&wtf,     g_wtf);
    cudaGetSymbolAddress((void**)&bf,      g_bf);

    const int SMEM = (64 * 136 + 128 * 136) * 2;   // 52,224 B
    cudaFuncSetAttribute(gemm_mma_kernel<128, true>,  cudaFuncAttributeMaxDynamicSharedMemorySize, SMEM);
    cudaFuncSetAttribute(gemm_mma_kernel<128, false>, cudaFuncAttributeMaxDynamicSharedMemorySize, SMEM);
    cudaFuncSetAttribute(gemm_mma_kernel<64, false>,  cudaFuncAttributeMaxDynamicSharedMemorySize, SMEM);

    const int T = 256;
    int nb_nodes   = (n + T - 1) / T;
    int nb_edges   = (E + T - 1) / T;
    int nb_agg     = (int)(((long long)n * 32 + T - 1) / T);
    int nt128      = (n + 63) / 64;      // row tiles for N_OUT=128 (BM=64)
    int nt64       = (n + 127) / 128;    // row tiles for N_OUT=64  (BM=128)
    int nb_scan    = (n + SCAN_B - 1) / SCAN_B;
    const int PERSIST = 148 * 4;         // 4 CTAs/SM persistent grid
    int gb128 = nt128 < PERSIST ? nt128 : PERSIST;
    int gb64  = nt64  < PERSIST ? nt64  : PERSIST;

    // ---- fork a side stream: {prep_all -> gemm1} runs concurrently with the CSR
    // chain. Graph replay executes the two branches in parallel. Resources are
    // created per call and leaked (kernel_launch runs only for correctness +
    // capture; no device-memory allocation is involved).
    cudaStream_t s2;
    cudaStreamCreateWithFlags(&s2, cudaStreamNonBlocking);
    cudaEvent_t evFork, evJoin;
    cudaEventCreateWithFlags(&evFork, cudaEventDisableTiming);
    cudaEventCreateWithFlags(&evJoin, cudaEventDisableTiming);

    cudaEventRecord(evFork, 0);
    cudaStreamWaitEvent(s2, evFork, 0);

    // side branch: weight prep + layer-1 GEMM (independent of edges)
    prep_all_kernel<<<(41024 + T - 1) / T, T, 0, s2>>>(W1, W2, W3, Wo, b3, bo, wt1, wt2, wtf, bf);
    gemm_mma_kernel<128, true><<<gb128, 256, SMEM, s2>>>(x, wt1, hA, n, nt128);
    cudaEventRecord(evJoin, s2);

    // main branch: CSR build + normalization
    zero_kernel<<<nb_nodes, T>>>(cnt, n);
    count_kernel<<<nb_edges, T>>>(dst, cnt, lpos, E);
    block_scan_kernel<<<nb_scan, SCAN_B>>>(cnt, rowptr, partial, isq, n);
    partial_scan_kernel<<<1, 32>>>(partial, nb_scan);
    add_offsets_kernel<<<nb_nodes, T>>>(rowptr, partial, n, nb_scan);
    fill_kernel<<<nb_edges, T>>>(src, dst, isq, rowptr, lpos, epack, E);

    // join: agg1 needs both gemm1 (s2) and fill (main)
    cudaStreamWaitEvent(0, evJoin, 0);

    // ---- layer 1 agg: h1 = relu(agg(x@W1) + b1) ----
    agg_kernel<true><<<nb_agg, T>>>(hA, rowptr, epack, isq, b1, hB, n);
    // ---- layer 2 ----
    gemm_mma_kernel<128, false><<<gb128, 256, SMEM>>>(hB, wt2, hA, n, nt128);
    agg_kernel<true><<<nb_agg, T>>>(hA, rowptr, epack, isq, b2, hB, n);
    // ---- layer 3 + output fused ----
    gemm_mma_kernel<64, false><<<gb64, 256, SMEM>>>(hB, wtf, hA, n, nt64);
    agg64_kernel<<<nb_agg, T>>>(hA, rowptr, epack, isq, bf, (float*)d_out, n);
}